// round 5
// baseline (speedup 1.0000x reference)
#include <cuda_runtime.h>
#include <cuda_fp16.h>
#include <math.h>

#define NN 100000
#define NE 1000000
#define DIM 64
#define KSTEPS 10
#define FULLMASK 0xffffffffu

// ---------------- static scratch (no allocations allowed) ----------------
__device__ int     g_out_deg[NN];
__device__ int     g_in_deg[NN];
__device__ float   g_src_norm[NN];
__device__ float   g_dst_norm[NN];
__device__ int     g_row_ptr[NN + 1];
__device__ int     g_fill[NN];
__device__ __align__(16)  uint2   g_edge[NE];   // .x = src id, .y = bits(fp32 weight)
__device__ __align__(128) __half2 g_y0[(size_t)NN * (DIM / 2)];
__device__ __align__(128) __half2 g_y1[(size_t)NN * (DIM / 2)];
__device__ __align__(128) __half2 g_fh[(size_t)NN * (DIM / 2)];  // fp16 feat cache
__device__ int     g_is64;

__device__ __forceinline__ int edge_at(const int* __restrict__ b, int i, int is64) {
    return b[is64 ? (i << 1) : i];
}

// ---------------- init: zero counters + dtype detect ----------------
__global__ void k_init0(const int* __restrict__ src32, int n) {
    int i = blockIdx.x * blockDim.x + threadIdx.x;
    if (i < n) { g_out_deg[i] = 0; g_in_deg[i] = 0; g_fill[i] = 0; }
    if (i == 0) g_is64 = 1;
    // block 0 probes the first 8KB: int64 data has all-zero odd words
    if (blockIdx.x == 0) {
        for (int j = threadIdx.x; j < 1024; j += blockDim.x)
            if (src32[2 * j + 1] != 0) g_is64 = 0;
    }
}

__global__ void k_count(const int* __restrict__ src,
                        const int* __restrict__ dst, int e) {
    int i = blockIdx.x * blockDim.x + threadIdx.x;
    int is64 = g_is64;
    if (i < e) {
        atomicAdd(&g_out_deg[edge_at(src, i, is64)], 1);
        atomicAdd(&g_in_deg[edge_at(dst, i, is64)], 1);
    }
}

// norms + fp16 feat cache (counts are final)
__global__ void k_prep(const float* __restrict__ feat, int n, int n32) {
    int i = blockIdx.x * blockDim.x + threadIdx.x;
    if (i < n) {
        g_src_norm[i] = rsqrtf(fmaxf((float)g_out_deg[i], 1.0f));
        g_dst_norm[i] = rsqrtf(fmaxf((float)g_in_deg[i], 1.0f));
    }
    if (i < n32) {
        float2 f = *(const float2*)(feat + (size_t)i * 2);
        g_fh[i] = __floats2half2_rn(f.x, f.y);
    }
}

// single-kernel exclusive scan of g_in_deg -> g_row_ptr (1 block, 1024 thr)
#define SCAN_T 1024
__global__ void k_scan(int n, int etotal) {
    __shared__ int sh[SCAN_T];
    int tid = threadIdx.x;
    int chunk = (n + SCAN_T - 1) / SCAN_T;
    int beg = tid * chunk;
    int end = beg + chunk < n ? beg + chunk : n;

    int sum = 0;
    for (int i = beg; i < end; i++) sum += g_in_deg[i];
    sh[tid] = sum;
    __syncthreads();
#pragma unroll
    for (int off = 1; off < SCAN_T; off <<= 1) {
        int t = (tid >= off) ? sh[tid - off] : 0;
        __syncthreads();
        sh[tid] += t;
        __syncthreads();
    }
    int run = sh[tid] - sum;     // exclusive prefix of this thread's chunk
    for (int i = beg; i < end; i++) {
        int v = g_in_deg[i];
        g_row_ptr[i] = run;
        run += v;
    }
    if (tid == SCAN_T - 1) g_row_ptr[n] = etotal;
}

__global__ void k_fill(const int* __restrict__ src,
                       const int* __restrict__ dst, int e) {
    int i = blockIdx.x * blockDim.x + threadIdx.x;
    int is64 = g_is64;
    if (i < e) {
        int s = edge_at(src, i, is64);
        int d = edge_at(dst, i, is64);
        int pos = g_row_ptr[d] + atomicAdd(&g_fill[d], 1);
        float w = g_src_norm[s] * g_dst_norm[d];
        g_edge[pos] = make_uint2((unsigned)s, __float_as_uint(w));
    }
}

// ---------------- Horner propagation ----------------
// y_K = w_K*f folded into first step: result = w_k*f + gs*sum (gs=w_K first, else 1).
// Warp per node; HALF-warp per edge: lane owns 4 cols (8B), 2 edges in flight
// per gather LDG.64. Combine halves with shfl_xor(16) once per node.
__device__ __forceinline__ void acc4(float w, uint2 v,
                                     float& a0, float& a1, float& a2, float& a3) {
    float2 p = __half22float2(*(__half2*)&v.x);
    float2 q = __half22float2(*(__half2*)&v.y);
    a0 = fmaf(w, p.x, a0); a1 = fmaf(w, p.y, a1);
    a2 = fmaf(w, q.x, a2); a3 = fmaf(w, q.y, a3);
}

__global__ void __launch_bounds__(256)
k_step(const __half2* __restrict__ yin, __half2* __restrict__ yout,
       const __half2* __restrict__ fh, const float* __restrict__ feat,
       float* __restrict__ out, float wk, float gs, int n, int last) {
    int t = blockIdx.x * blockDim.x + threadIdx.x;
    int node = t >> 5;
    if (node >= n) return;
    int lane = t & 31;
    int half = lane >> 4;      // which edge of the pair
    int hl   = lane & 15;      // column group: cols hl*4 .. hl*4+3

    int base = g_row_ptr[node];
    int deg  = g_row_ptr[node + 1] - base;

    float a0 = 0.f, a1 = 0.f, a2 = 0.f, a3 = 0.f;
    int i = 0;
    // 2 pair-iterations unrolled: 4 edges, 2 gather LDG.64 + 2 edge LDG.64 in flight
    for (; i + 4 <= deg; i += 4) {
        uint2 eA = g_edge[base + i + half];
        uint2 eB = g_edge[base + i + 2 + half];
        uint2 vA = *(const uint2*)(yin + (size_t)eA.x * 32 + hl * 2);
        uint2 vB = *(const uint2*)(yin + (size_t)eB.x * 32 + hl * 2);
        acc4(__uint_as_float(eA.y), vA, a0, a1, a2, a3);
        acc4(__uint_as_float(eB.y), vB, a0, a1, a2, a3);
    }
    for (; i < deg; i += 2) {
        if (i + half < deg) {
            uint2 ed = g_edge[base + i + half];
            uint2 v  = *(const uint2*)(yin + (size_t)ed.x * 32 + hl * 2);
            acc4(__uint_as_float(ed.y), v, a0, a1, a2, a3);
        }
    }

    // combine the two half-warps
    a0 += __shfl_xor_sync(FULLMASK, a0, 16);
    a1 += __shfl_xor_sync(FULLMASK, a1, 16);
    a2 += __shfl_xor_sync(FULLMASK, a2, 16);
    a3 += __shfl_xor_sync(FULLMASK, a3, 16);

    if (lane < 16) {
        if (last) {
            float4 f = *(const float4*)(feat + (size_t)node * DIM + hl * 4);
            float4 r;
            r.x = fmaf(wk, f.x, gs * a0);
            r.y = fmaf(wk, f.y, gs * a1);
            r.z = fmaf(wk, f.z, gs * a2);
            r.w = fmaf(wk, f.w, gs * a3);
            *(float4*)(out + (size_t)node * DIM + hl * 4) = r;
        } else {
            uint2 fv = *(const uint2*)(fh + (size_t)node * 32 + hl * 2);
            float2 p = __half22float2(*(__half2*)&fv.x);
            float2 q = __half22float2(*(__half2*)&fv.y);
            __half2 h0 = __floats2half2_rn(fmaf(wk, p.x, gs * a0),
                                           fmaf(wk, p.y, gs * a1));
            __half2 h1 = __floats2half2_rn(fmaf(wk, q.x, gs * a2),
                                           fmaf(wk, q.y, gs * a3));
            uint2 o;
            o.x = *(unsigned*)&h0;
            o.y = *(unsigned*)&h1;
            *(uint2*)(yout + (size_t)node * 32 + hl * 2) = o;
        }
    }
}

// ---------------- launch ----------------
extern "C" void kernel_launch(void* const* d_in, const int* in_sizes, int n_in,
                              void* d_out, int out_size) {
    const float* feat  = (const float*)d_in[0];
    const int*   src32 = (const int*)d_in[1];
    const int*   dst32 = (const int*)d_in[2];
    float* out = (float*)d_out;

    int n = in_sizes[0] / DIM;   // 100000
    int e = in_sizes[1];         // 1000000

    void *p0, *p1, *p2;
    cudaGetSymbolAddress(&p0, g_y0);
    cudaGetSymbolAddress(&p1, g_y1);
    cudaGetSymbolAddress(&p2, g_fh);
    __half2* y0 = (__half2*)p0;
    __half2* y1 = (__half2*)p1;
    __half2* fh = (__half2*)p2;

    // log weights: w[j] = log(BETA + 1 + j)/denom, BETA = 2
    double logs[KSTEPS + 1]; double denom = 0.0;
    for (int j = 0; j <= KSTEPS; j++) { logs[j] = log(3.0 + (double)j); denom += logs[j]; }

    int nb_n = (n + 255) / 256;
    int nb_e = (e + 255) / 256;
    int n32  = n * 32;

    k_init0<<<nb_n, 256>>>(src32, n);
    k_count<<<nb_e, 256>>>(src32, dst32, e);
    k_prep <<<(n32 + 255) / 256, 256>>>(feat, n, n32);
    k_scan <<<1, SCAN_T>>>(n, e);
    k_fill <<<nb_e, 256>>>(src32, dst32, e);

    int nb_s = (n32 + 255) / 256;
    const __half2* yin = fh;          // first step gathers feat directly
    __half2* yout = y0;
    for (int k = KSTEPS - 1; k >= 0; k--) {
        float gs = (k == KSTEPS - 1) ? (float)(logs[KSTEPS] / denom) : 1.0f;
        k_step<<<nb_s, 256>>>(yin, yout, fh, feat, out,
                              (float)(logs[k] / denom), gs, n, k == 0);
        yin = yout;
        yout = (yout == y0) ? y1 : y0;
    }
}

// round 6
// speedup vs baseline: 1.3452x; 1.3452x over previous
#include <cuda_runtime.h>
#include <cuda_fp16.h>
#include <math.h>

#define NN 100000
#define NE 1000000
#define DIM 64
#define KSTEPS 10
#define FULLMASK 0xffffffffu

// ---------------- static scratch (no allocations allowed) ----------------
__device__ int     g_out_deg[NN];
__device__ int     g_in_deg[NN];
__device__ float   g_src_norm[NN];
__device__ float   g_dst_norm[NN];
__device__ int     g_row_ptr[NN + 1];
__device__ int     g_fill[NN];
__device__ __align__(16)  uint2   g_edge[NE];   // .x = src id, .y = bits(fp32 weight)
__device__ __align__(128) __half2 g_y0[(size_t)NN * (DIM / 2)];
__device__ __align__(128) __half2 g_y1[(size_t)NN * (DIM / 2)];
__device__ __align__(128) __half2 g_fh[(size_t)NN * (DIM / 2)];  // fp16 feat cache
__device__ int     g_blk[128];
__device__ int     g_is64;

__device__ __forceinline__ int edge_at(const int* __restrict__ b, int i, int is64) {
    return b[is64 ? (i << 1) : i];
}

// ---------------- init: zero counters + dtype detect ----------------
__global__ void k_init0(const int* __restrict__ src32, int n) {
    int i = blockIdx.x * blockDim.x + threadIdx.x;
    if (i < n) { g_out_deg[i] = 0; g_in_deg[i] = 0; g_fill[i] = 0; }
    if (i == 0) g_is64 = 1;
    // block 0 probes the first 8KB: int64 data has all-zero odd words
    if (blockIdx.x == 0) {
        for (int j = threadIdx.x; j < 1024; j += blockDim.x)
            if (src32[2 * j + 1] != 0) g_is64 = 0;
    }
}

__global__ void k_count(const int* __restrict__ src,
                        const int* __restrict__ dst, int e) {
    int i = blockIdx.x * blockDim.x + threadIdx.x;
    int is64 = g_is64;
    if (i < e) {
        atomicAdd(&g_out_deg[edge_at(src, i, is64)], 1);
        atomicAdd(&g_in_deg[edge_at(dst, i, is64)], 1);
    }
}

// scan1: block-local exclusive scan of in_deg; also computes norms + fp16 feat.
__global__ void k_scan1(const float* __restrict__ feat, int n, int n32) {
    __shared__ int sh[1024];
    int gid = blockIdx.x * 1024 + threadIdx.x;
    int v = (gid < n) ? g_in_deg[gid] : 0;
    if (gid < n) {
        g_src_norm[gid] = rsqrtf(fmaxf((float)g_out_deg[gid], 1.0f));
        g_dst_norm[gid] = rsqrtf(fmaxf((float)v, 1.0f));
    }
    sh[threadIdx.x] = v;
    __syncthreads();
#pragma unroll
    for (int off = 1; off < 1024; off <<= 1) {
        int t = (threadIdx.x >= (unsigned)off) ? sh[threadIdx.x - off] : 0;
        __syncthreads();
        sh[threadIdx.x] += t;
        __syncthreads();
    }
    if (gid < n) g_row_ptr[gid] = sh[threadIdx.x] - v;   // exclusive within block
    if (threadIdx.x == 1023) g_blk[blockIdx.x] = sh[1023];

    // fp16 feat cache rides along (uses a disjoint index range; n32 = 32*n)
    for (int i = gid; i < n32; i += gridDim.x * 1024) {
        float2 f = *(const float2*)(feat + (size_t)i * 2);
        g_fh[i] = __floats2half2_rn(f.x, f.y);
    }
}

// scan2: warp-parallel exclusive scan of the (<=128) block sums
__global__ void k_scan2(int nblk, int etotal, int n) {
    __shared__ int warp_tot[4];
    int tid = threadIdx.x;              // 128 threads
    int v = (tid < nblk) ? g_blk[tid] : 0;
    int lane = tid & 31, w = tid >> 5;
    int x = v;
#pragma unroll
    for (int off = 1; off < 32; off <<= 1) {
        int t = __shfl_up_sync(FULLMASK, x, off);
        if (lane >= off) x += t;
    }
    if (lane == 31) warp_tot[w] = x;
    __syncthreads();
    int add = 0;
    for (int j = 0; j < w; j++) add += warp_tot[j];
    if (tid < nblk) g_blk[tid] = add + x - v;   // exclusive prefix
    if (tid == 0) g_row_ptr[n] = etotal;
}

__global__ void k_scan3(int n) {
    int gid = blockIdx.x * 1024 + threadIdx.x;
    if (gid < n) g_row_ptr[gid] += g_blk[blockIdx.x];
}

__global__ void k_fill(const int* __restrict__ src,
                       const int* __restrict__ dst, int e) {
    int i = blockIdx.x * blockDim.x + threadIdx.x;
    int is64 = g_is64;
    if (i < e) {
        int s = edge_at(src, i, is64);
        int d = edge_at(dst, i, is64);
        int pos = g_row_ptr[d] + atomicAdd(&g_fill[d], 1);
        float w = g_src_norm[s] * g_dst_norm[d];
        g_edge[pos] = make_uint2((unsigned)s, __float_as_uint(w));
    }
}

// ---------------- Horner propagation ----------------
// y_K = w_K*f folded into first step: result = w_k*f + gs*sum (gs = w_K on the
// first step, else 1). Warp per node, lane owns one half2 (2 of 64 cols).
__global__ void __launch_bounds__(256)
k_step(const __half2* __restrict__ yin, __half2* __restrict__ yout,
       const __half2* __restrict__ fh, const float* __restrict__ feat,
       float* __restrict__ out, float wk, float gs, int n, int last) {
    int t = blockIdx.x * blockDim.x + threadIdx.x;
    int node = t >> 5;
    int lane = t & 31;
    if (node >= n) return;
    int beg = g_row_ptr[node];
    int end = g_row_ptr[node + 1];

    float ax = 0.0f, ay = 0.0f;
    int e = beg;
    // 4-way unroll: four independent 128B gathers in flight per warp
    for (; e + 4 <= end; e += 4) {
        uint2 e0 = g_edge[e],     e1 = g_edge[e + 1];
        uint2 e2 = g_edge[e + 2], e3 = g_edge[e + 3];
        float2 v0 = __half22float2(yin[(size_t)e0.x * 32 + lane]);
        float2 v1 = __half22float2(yin[(size_t)e1.x * 32 + lane]);
        float2 v2 = __half22float2(yin[(size_t)e2.x * 32 + lane]);
        float2 v3 = __half22float2(yin[(size_t)e3.x * 32 + lane]);
        float w0 = __uint_as_float(e0.y), w1 = __uint_as_float(e1.y);
        float w2 = __uint_as_float(e2.y), w3 = __uint_as_float(e3.y);
        ax += w0 * v0.x; ay += w0 * v0.y;
        ax += w1 * v1.x; ay += w1 * v1.y;
        ax += w2 * v2.x; ay += w2 * v2.y;
        ax += w3 * v3.x; ay += w3 * v3.y;
    }
    for (; e < end; e++) {
        uint2 ed = g_edge[e];
        float2 v = __half22float2(yin[(size_t)ed.x * 32 + lane]);
        float w = __uint_as_float(ed.y);
        ax += w * v.x; ay += w * v.y;
    }

    if (last) {
        // fp32 feat for the final direct-feat term; fp32 out
        float2 f = *(const float2*)(feat + (size_t)node * DIM + lane * 2);
        *(float2*)(out + (size_t)node * DIM + lane * 2) =
            make_float2(fmaf(wk, f.x, gs * ax), fmaf(wk, f.y, gs * ay));
    } else {
        float2 f = __half22float2(fh[(size_t)node * 32 + lane]);
        yout[(size_t)node * 32 + lane] =
            __floats2half2_rn(fmaf(wk, f.x, gs * ax), fmaf(wk, f.y, gs * ay));
    }
}

// ---------------- launch ----------------
extern "C" void kernel_launch(void* const* d_in, const int* in_sizes, int n_in,
                              void* d_out, int out_size) {
    const float* feat  = (const float*)d_in[0];
    const int*   src32 = (const int*)d_in[1];
    const int*   dst32 = (const int*)d_in[2];
    float* out = (float*)d_out;

    int n = in_sizes[0] / DIM;   // 100000
    int e = in_sizes[1];         // 1000000

    void *p0, *p1, *p2;
    cudaGetSymbolAddress(&p0, g_y0);
    cudaGetSymbolAddress(&p1, g_y1);
    cudaGetSymbolAddress(&p2, g_fh);
    __half2* y0 = (__half2*)p0;
    __half2* y1 = (__half2*)p1;
    __half2* fh = (__half2*)p2;

    // log weights: w[j] = log(BETA + 1 + j)/denom, BETA = 2
    double logs[KSTEPS + 1]; double denom = 0.0;
    for (int j = 0; j <= KSTEPS; j++) { logs[j] = log(3.0 + (double)j); denom += logs[j]; }

    int nb_n = (n + 255) / 256;
    int nb_e = (e + 255) / 256;
    int nblk = (n + 1023) / 1024;     // 98
    int n32  = n * 32;

    k_init0<<<nb_n, 256>>>(src32, n);
    k_count<<<nb_e, 256>>>(src32, dst32, e);
    k_scan1<<<nblk, 1024>>>(feat, n, n32);
    k_scan2<<<1, 128>>>(nblk, e, n);
    k_scan3<<<nblk, 1024>>>(n);
    k_fill <<<nb_e, 256>>>(src32, dst32, e);

    int nb_s = (n32 + 255) / 256;
    const __half2* yin = fh;          // first step gathers feat directly
    __half2* yout = y0;
    for (int k = KSTEPS - 1; k >= 0; k--) {
        float gs = (k == KSTEPS - 1) ? (float)(logs[KSTEPS] / denom) : 1.0f;
        k_step<<<nb_s, 256>>>(yin, yout, fh, feat, out,
                              (float)(logs[k] / denom), gs, n, k == 0);
        yin = yout;
        yout = (yout == y0) ? y1 : y0;
    }
}

// round 7
// speedup vs baseline: 1.4654x; 1.0894x over previous
#include <cuda_runtime.h>
#include <cuda_fp16.h>
#include <math.h>

#define NN 100000
#define NE 1000000
#define DIM 64
#define KSTEPS 10
#define FULLMASK 0xffffffffu

// ---------------- static scratch (no allocations allowed) ----------------
__device__ int     g_out_deg[NN];
__device__ int     g_in_deg[NN];
__device__ float   g_src_norm[NN];
__device__ float   g_dst_norm[NN];
__device__ int     g_row_ptr[NN + 1];
__device__ int     g_fill[NN];
__device__ __align__(16)  uint2   g_edge[NE];   // .x = src id, .y = bits(fp32 weight)
// y / feat-cache stored as 16B granules: row = 8 x uint4 (64 halves)
__device__ __align__(128) uint4 g_y0[(size_t)NN * 8];
__device__ __align__(128) uint4 g_y1[(size_t)NN * 8];
__device__ __align__(128) uint4 g_fh[(size_t)NN * 8];
__device__ int     g_blk[128];
__device__ int     g_is64;

__device__ __forceinline__ int edge_at(const int* __restrict__ b, int i, int is64) {
    return b[is64 ? (i << 1) : i];
}

// ---------------- init: zero counters + dtype detect ----------------
__global__ void k_init0(const int* __restrict__ src32, int n) {
    int i = blockIdx.x * blockDim.x + threadIdx.x;
    if (i < n) { g_out_deg[i] = 0; g_in_deg[i] = 0; g_fill[i] = 0; }
    if (i == 0) g_is64 = 1;
    if (blockIdx.x == 0) {   // int64 data has all-zero odd 32-bit words
        for (int j = threadIdx.x; j < 1024; j += blockDim.x)
            if (src32[2 * j + 1] != 0) g_is64 = 0;
    }
}

__global__ void k_count(const int* __restrict__ src,
                        const int* __restrict__ dst, int e) {
    int i = blockIdx.x * blockDim.x + threadIdx.x;
    int is64 = g_is64;
    if (i < e) {
        atomicAdd(&g_out_deg[edge_at(src, i, is64)], 1);
        atomicAdd(&g_in_deg[edge_at(dst, i, is64)], 1);
    }
}

// scan1: block-local exclusive scan of in_deg; also norms + fp16 feat cache.
__global__ void k_scan1(const float* __restrict__ feat, int n, int n8) {
    __shared__ int sh[1024];
    int gid = blockIdx.x * 1024 + threadIdx.x;
    int v = (gid < n) ? g_in_deg[gid] : 0;
    if (gid < n) {
        g_src_norm[gid] = rsqrtf(fmaxf((float)g_out_deg[gid], 1.0f));
        g_dst_norm[gid] = rsqrtf(fmaxf((float)v, 1.0f));
    }
    sh[threadIdx.x] = v;
    __syncthreads();
#pragma unroll
    for (int off = 1; off < 1024; off <<= 1) {
        int t = (threadIdx.x >= (unsigned)off) ? sh[threadIdx.x - off] : 0;
        __syncthreads();
        sh[threadIdx.x] += t;
        __syncthreads();
    }
    if (gid < n) g_row_ptr[gid] = sh[threadIdx.x] - v;
    if (threadIdx.x == 1023) g_blk[blockIdx.x] = sh[1023];

    // fp16 feat cache: one 16B granule (8 floats -> 8 halves) per index
    for (int i = gid; i < n8; i += gridDim.x * 1024) {
        float4 f0 = *(const float4*)(feat + (size_t)i * 8);
        float4 f1 = *(const float4*)(feat + (size_t)i * 8 + 4);
        uint4 o;
        __half2 h;
        h = __floats2half2_rn(f0.x, f0.y); o.x = *(unsigned*)&h;
        h = __floats2half2_rn(f0.z, f0.w); o.y = *(unsigned*)&h;
        h = __floats2half2_rn(f1.x, f1.y); o.z = *(unsigned*)&h;
        h = __floats2half2_rn(f1.z, f1.w); o.w = *(unsigned*)&h;
        g_fh[i] = o;
    }
}

// scan2: warp-parallel exclusive scan of the (<=128) block sums
__global__ void k_scan2(int nblk, int etotal, int n) {
    __shared__ int warp_tot[4];
    int tid = threadIdx.x;
    int v = (tid < nblk) ? g_blk[tid] : 0;
    int lane = tid & 31, w = tid >> 5;
    int x = v;
#pragma unroll
    for (int off = 1; off < 32; off <<= 1) {
        int t = __shfl_up_sync(FULLMASK, x, off);
        if (lane >= off) x += t;
    }
    if (lane == 31) warp_tot[w] = x;
    __syncthreads();
    int add = 0;
    for (int j = 0; j < w; j++) add += warp_tot[j];
    if (tid < nblk) g_blk[tid] = add + x - v;
    if (tid == 0) g_row_ptr[n] = etotal;
}

__global__ void k_scan3(int n) {
    int gid = blockIdx.x * 1024 + threadIdx.x;
    if (gid < n) g_row_ptr[gid] += g_blk[blockIdx.x];
}

__global__ void k_fill(const int* __restrict__ src,
                       const int* __restrict__ dst, int e) {
    int i = blockIdx.x * blockDim.x + threadIdx.x;
    int is64 = g_is64;
    if (i < e) {
        int s = edge_at(src, i, is64);
        int d = edge_at(dst, i, is64);
        int pos = g_row_ptr[d] + atomicAdd(&g_fill[d], 1);
        float w = g_src_norm[s] * g_dst_norm[d];
        g_edge[pos] = make_uint2((unsigned)s, __float_as_uint(w));
    }
}

// ---------------- Horner propagation ----------------
// result = w_k*f + gs*sum (gs = w_K on the first step, else 1).
// Warp per node; QUARTER-warp per edge: lane owns 16B (8 cols) of the 128B
// fp16 row; one LDG.128 gathers for 4 edges at once. Quarter partials
// combined once per node with shfl_xor(8)+shfl_xor(16).
__device__ __forceinline__ void acc8(float w, uint4 v, float* a) {
    float2 p;
    p = __half22float2(*(__half2*)&v.x); a[0] = fmaf(w, p.x, a[0]); a[1] = fmaf(w, p.y, a[1]);
    p = __half22float2(*(__half2*)&v.y); a[2] = fmaf(w, p.x, a[2]); a[3] = fmaf(w, p.y, a[3]);
    p = __half22float2(*(__half2*)&v.z); a[4] = fmaf(w, p.x, a[4]); a[5] = fmaf(w, p.y, a[5]);
    p = __half22float2(*(__half2*)&v.w); a[6] = fmaf(w, p.x, a[6]); a[7] = fmaf(w, p.y, a[7]);
}

__global__ void __launch_bounds__(256)
k_step(const uint4* __restrict__ yin, uint4* __restrict__ yout,
       const uint4* __restrict__ fh, const float* __restrict__ feat,
       float* __restrict__ out, float wk, float gs, int n, int last) {
    int t = blockIdx.x * blockDim.x + threadIdx.x;
    int node = t >> 5;
    int lane = t & 31;
    if (node >= n) return;
    int q  = lane >> 3;     // quarter id: which edge of the 4-batch
    int g  = lane & 7;      // granule id: cols g*8 .. g*8+7

    int beg = g_row_ptr[node];
    int end = g_row_ptr[node + 1];

    float a[8] = {0.f, 0.f, 0.f, 0.f, 0.f, 0.f, 0.f, 0.f};
    int i = beg;
    // 2 batches (8 edges) in flight: 2x LDG.64 edge + 2x LDG.128 gather
    for (; i + 8 <= end; i += 8) {
        uint2 eA = g_edge[i + q];
        uint2 eB = g_edge[i + 4 + q];
        uint4 vA = yin[(size_t)eA.x * 8 + g];
        uint4 vB = yin[(size_t)eB.x * 8 + g];
        acc8(__uint_as_float(eA.y), vA, a);
        acc8(__uint_as_float(eB.y), vB, a);
    }
    for (; i < end; i += 4) {
        if (i + q < end) {
            uint2 ed = g_edge[i + q];
            uint4 v  = yin[(size_t)ed.x * 8 + g];
            acc8(__uint_as_float(ed.y), v, a);
        }
    }

    // combine the 4 quarters (partials live at same g across quarters)
#pragma unroll
    for (int j = 0; j < 8; j++) {
        a[j] += __shfl_xor_sync(FULLMASK, a[j], 8);
        a[j] += __shfl_xor_sync(FULLMASK, a[j], 16);
    }

    if (lane < 8) {   // lane == g owns cols g*8..g*8+7
        if (last) {
            const float* fp = feat + (size_t)node * DIM + lane * 8;
            float* op = out + (size_t)node * DIM + lane * 8;
            float4 f0 = *(const float4*)fp;
            float4 f1 = *(const float4*)(fp + 4);
            float4 r0, r1;
            r0.x = fmaf(wk, f0.x, gs * a[0]); r0.y = fmaf(wk, f0.y, gs * a[1]);
            r0.z = fmaf(wk, f0.z, gs * a[2]); r0.w = fmaf(wk, f0.w, gs * a[3]);
            r1.x = fmaf(wk, f1.x, gs * a[4]); r1.y = fmaf(wk, f1.y, gs * a[5]);
            r1.z = fmaf(wk, f1.z, gs * a[6]); r1.w = fmaf(wk, f1.w, gs * a[7]);
            *(float4*)op = r0;
            *(float4*)(op + 4) = r1;
        } else {
            uint4 fv = fh[(size_t)node * 8 + lane];
            float2 p;
            uint4 o;
            __half2 h;
            p = __half22float2(*(__half2*)&fv.x);
            h = __floats2half2_rn(fmaf(wk, p.x, gs * a[0]), fmaf(wk, p.y, gs * a[1]));
            o.x = *(unsigned*)&h;
            p = __half22float2(*(__half2*)&fv.y);
            h = __floats2half2_rn(fmaf(wk, p.x, gs * a[2]), fmaf(wk, p.y, gs * a[3]));
            o.y = *(unsigned*)&h;
            p = __half22float2(*(__half2*)&fv.z);
            h = __floats2half2_rn(fmaf(wk, p.x, gs * a[4]), fmaf(wk, p.y, gs * a[5]));
            o.z = *(unsigned*)&h;
            p = __half22float2(*(__half2*)&fv.w);
            h = __floats2half2_rn(fmaf(wk, p.x, gs * a[6]), fmaf(wk, p.y, gs * a[7]));
            o.w = *(unsigned*)&h;
            yout[(size_t)node * 8 + lane] = o;
        }
    }
}

// ---------------- launch ----------------
extern "C" void kernel_launch(void* const* d_in, const int* in_sizes, int n_in,
                              void* d_out, int out_size) {
    const float* feat  = (const float*)d_in[0];
    const int*   src32 = (const int*)d_in[1];
    const int*   dst32 = (const int*)d_in[2];
    float* out = (float*)d_out;

    int n = in_sizes[0] / DIM;   // 100000
    int e = in_sizes[1];         // 1000000

    void *p0, *p1, *p2;
    cudaGetSymbolAddress(&p0, g_y0);
    cudaGetSymbolAddress(&p1, g_y1);
    cudaGetSymbolAddress(&p2, g_fh);
    uint4* y0 = (uint4*)p0;
    uint4* y1 = (uint4*)p1;
    uint4* fh = (uint4*)p2;

    // log weights: w[j] = log(BETA + 1 + j)/denom, BETA = 2
    double logs[KSTEPS + 1]; double denom = 0.0;
    for (int j = 0; j <= KSTEPS; j++) { logs[j] = log(3.0 + (double)j); denom += logs[j]; }

    int nb_n = (n + 255) / 256;
    int nb_e = (e + 255) / 256;
    int nblk = (n + 1023) / 1024;     // 98
    int n8   = n * 8;

    k_init0<<<nb_n, 256>>>(src32, n);
    k_count<<<nb_e, 256>>>(src32, dst32, e);
    k_scan1<<<nblk, 1024>>>(feat, n, n8);
    k_scan2<<<1, 128>>>(nblk, e, n);
    k_scan3<<<nblk, 1024>>>(n);
    k_fill <<<nb_e, 256>>>(src32, dst32, e);

    int nb_s = (n * 32 + 255) / 256;
    const uint4* yin = fh;            // first step gathers feat directly
    uint4* yout = y0;
    for (int k = KSTEPS - 1; k >= 0; k--) {
        float gs = (k == KSTEPS - 1) ? (float)(logs[KSTEPS] / denom) : 1.0f;
        k_step<<<nb_s, 256>>>(yin, yout, fh, feat, out,
                              (float)(logs[k] / denom), gs, n, k == 0);
        yin = yout;
        yout = (yout == y0) ? y1 : y0;
    }
}

// round 8
// speedup vs baseline: 2.0030x; 1.3668x over previous
#include <cuda_runtime.h>
#include <cuda_fp16.h>
#include <math.h>

#define NN 100000
#define NE 1000000
#define DIM 64
#define KSTEPS 10
#define FULLMASK 0xffffffffu

// ---------------- static scratch (no allocations allowed) ----------------
__device__ int     g_out_deg[NN];
__device__ int     g_in_deg[NN];
__device__ float   g_src_norm[NN];
__device__ float   g_dst_norm[NN];
__device__ int     g_row_ptr[NN + 1];
__device__ int     g_fill[NN];
__device__ __align__(16)  uint2   g_edge[NE];   // .x = src id, .y = bits(fp32 weight)
// y / feat-cache stored as 16B granules: row = 8 x uint4 (64 halves)
__device__ __align__(128) uint4 g_y0[(size_t)NN * 8];
__device__ __align__(128) uint4 g_y1[(size_t)NN * 8];
__device__ __align__(128) uint4 g_fh[(size_t)NN * 8];
__device__ int     g_blk[128];
__device__ int     g_is64;

__device__ __forceinline__ int edge_at(const int* __restrict__ b, int i, int is64) {
    return b[is64 ? (i << 1) : i];
}

// ---------------- init: zero counters + dtype detect ----------------
__global__ void k_init0(const int* __restrict__ src32, int n) {
    int i = blockIdx.x * blockDim.x + threadIdx.x;
    if (i < n) { g_out_deg[i] = 0; g_in_deg[i] = 0; g_fill[i] = 0; }
    if (i == 0) g_is64 = 1;
    if (blockIdx.x == 0) {   // int64 data has all-zero odd 32-bit words
        for (int j = threadIdx.x; j < 1024; j += blockDim.x)
            if (src32[2 * j + 1] != 0) g_is64 = 0;
    }
}

__global__ void k_count(const int* __restrict__ src,
                        const int* __restrict__ dst, int e) {
    int i = blockIdx.x * blockDim.x + threadIdx.x;
    int is64 = g_is64;
    if (i < e) {
        atomicAdd(&g_out_deg[edge_at(src, i, is64)], 1);
        atomicAdd(&g_in_deg[edge_at(dst, i, is64)], 1);
    }
}

// scan1: block-local exclusive scan of in_deg; also norms + fp16 feat cache.
__global__ void k_scan1(const float* __restrict__ feat, int n, int n8) {
    __shared__ int sh[1024];
    int gid = blockIdx.x * 1024 + threadIdx.x;
    int v = (gid < n) ? g_in_deg[gid] : 0;
    if (gid < n) {
        g_src_norm[gid] = rsqrtf(fmaxf((float)g_out_deg[gid], 1.0f));
        g_dst_norm[gid] = rsqrtf(fmaxf((float)v, 1.0f));
    }
    sh[threadIdx.x] = v;
    __syncthreads();
#pragma unroll
    for (int off = 1; off < 1024; off <<= 1) {
        int t = (threadIdx.x >= (unsigned)off) ? sh[threadIdx.x - off] : 0;
        __syncthreads();
        sh[threadIdx.x] += t;
        __syncthreads();
    }
    if (gid < n) g_row_ptr[gid] = sh[threadIdx.x] - v;
    if (threadIdx.x == 1023) g_blk[blockIdx.x] = sh[1023];

    // fp16 feat cache: one 16B granule (8 floats -> 8 halves) per index
    for (int i = gid; i < n8; i += gridDim.x * 1024) {
        float4 f0 = *(const float4*)(feat + (size_t)i * 8);
        float4 f1 = *(const float4*)(feat + (size_t)i * 8 + 4);
        uint4 o;
        __half2 h;
        h = __floats2half2_rn(f0.x, f0.y); o.x = *(unsigned*)&h;
        h = __floats2half2_rn(f0.z, f0.w); o.y = *(unsigned*)&h;
        h = __floats2half2_rn(f1.x, f1.y); o.z = *(unsigned*)&h;
        h = __floats2half2_rn(f1.z, f1.w); o.w = *(unsigned*)&h;
        g_fh[i] = o;
    }
}

// scan2: warp-parallel exclusive scan of the (<=128) block sums
__global__ void k_scan2(int nblk, int etotal, int n) {
    __shared__ int warp_tot[4];
    int tid = threadIdx.x;
    int v = (tid < nblk) ? g_blk[tid] : 0;
    int lane = tid & 31, w = tid >> 5;
    int x = v;
#pragma unroll
    for (int off = 1; off < 32; off <<= 1) {
        int t = __shfl_up_sync(FULLMASK, x, off);
        if (lane >= off) x += t;
    }
    if (lane == 31) warp_tot[w] = x;
    __syncthreads();
    int add = 0;
    for (int j = 0; j < w; j++) add += warp_tot[j];
    if (tid < nblk) g_blk[tid] = add + x - v;
    if (tid == 0) g_row_ptr[n] = etotal;
}

__global__ void k_scan3(int n) {
    int gid = blockIdx.x * 1024 + threadIdx.x;
    if (gid < n) g_row_ptr[gid] += g_blk[blockIdx.x];
}

__global__ void k_fill(const int* __restrict__ src,
                       const int* __restrict__ dst, int e) {
    int i = blockIdx.x * blockDim.x + threadIdx.x;
    int is64 = g_is64;
    if (i < e) {
        int s = edge_at(src, i, is64);
        int d = edge_at(dst, i, is64);
        int pos = g_row_ptr[d] + atomicAdd(&g_fill[d], 1);
        float w = g_src_norm[s] * g_dst_norm[d];
        g_edge[pos] = make_uint2((unsigned)s, __float_as_uint(w));
    }
}

// ---------------- Horner propagation ----------------
// result = w_k*f + gs*sum (gs = w_K on the first step, else 1).
// QUARTER-WARP (8 lanes) per node: lane owns 16B (8 cols); one LDG.128 per
// edge covers the full 128B fp16 row within the quarter. No cross-lane
// reduction, no shared tail, all 32 lanes active in the epilogue.
__device__ __forceinline__ void acc8(float w, uint4 v, float* a) {
    float2 p;
    p = __half22float2(*(__half2*)&v.x); a[0] = fmaf(w, p.x, a[0]); a[1] = fmaf(w, p.y, a[1]);
    p = __half22float2(*(__half2*)&v.y); a[2] = fmaf(w, p.x, a[2]); a[3] = fmaf(w, p.y, a[3]);
    p = __half22float2(*(__half2*)&v.z); a[4] = fmaf(w, p.x, a[4]); a[5] = fmaf(w, p.y, a[5]);
    p = __half22float2(*(__half2*)&v.w); a[6] = fmaf(w, p.x, a[6]); a[7] = fmaf(w, p.y, a[7]);
}

__global__ void __launch_bounds__(256)
k_step(const uint4* __restrict__ yin, uint4* __restrict__ yout,
       const uint4* __restrict__ fh, const float* __restrict__ feat,
       float* __restrict__ out, float wk, float gs, int n, int last) {
    int t = blockIdx.x * blockDim.x + threadIdx.x;
    int node = t >> 3;        // quarter-warp per node
    if (node >= n) return;
    int g = t & 7;            // granule: cols g*8 .. g*8+7

    int beg = g_row_ptr[node];
    int end = g_row_ptr[node + 1];

    float a[8] = {0.f, 0.f, 0.f, 0.f, 0.f, 0.f, 0.f, 0.f};
    int i = beg;
    // 2 independent edge chains in flight per quarter (x4 quarters per warp)
    for (; i + 2 <= end; i += 2) {
        uint2 e0 = g_edge[i];
        uint2 e1 = g_edge[i + 1];
        uint4 v0 = yin[(size_t)e0.x * 8 + g];
        uint4 v1 = yin[(size_t)e1.x * 8 + g];
        acc8(__uint_as_float(e0.y), v0, a);
        acc8(__uint_as_float(e1.y), v1, a);
    }
    if (i < end) {
        uint2 ed = g_edge[i];
        uint4 v  = yin[(size_t)ed.x * 8 + g];
        acc8(__uint_as_float(ed.y), v, a);
    }

    if (last) {
        const float* fp = feat + (size_t)node * DIM + g * 8;
        float* op = out + (size_t)node * DIM + g * 8;
        float4 f0 = *(const float4*)fp;
        float4 f1 = *(const float4*)(fp + 4);
        float4 r0, r1;
        r0.x = fmaf(wk, f0.x, gs * a[0]); r0.y = fmaf(wk, f0.y, gs * a[1]);
        r0.z = fmaf(wk, f0.z, gs * a[2]); r0.w = fmaf(wk, f0.w, gs * a[3]);
        r1.x = fmaf(wk, f1.x, gs * a[4]); r1.y = fmaf(wk, f1.y, gs * a[5]);
        r1.z = fmaf(wk, f1.z, gs * a[6]); r1.w = fmaf(wk, f1.w, gs * a[7]);
        *(float4*)op = r0;
        *(float4*)(op + 4) = r1;
    } else {
        uint4 fv = fh[(size_t)node * 8 + g];
        float2 p;
        uint4 o;
        __half2 h;
        p = __half22float2(*(__half2*)&fv.x);
        h = __floats2half2_rn(fmaf(wk, p.x, gs * a[0]), fmaf(wk, p.y, gs * a[1]));
        o.x = *(unsigned*)&h;
        p = __half22float2(*(__half2*)&fv.y);
        h = __floats2half2_rn(fmaf(wk, p.x, gs * a[2]), fmaf(wk, p.y, gs * a[3]));
        o.y = *(unsigned*)&h;
        p = __half22float2(*(__half2*)&fv.z);
        h = __floats2half2_rn(fmaf(wk, p.x, gs * a[4]), fmaf(wk, p.y, gs * a[5]));
        o.z = *(unsigned*)&h;
        p = __half22float2(*(__half2*)&fv.w);
        h = __floats2half2_rn(fmaf(wk, p.x, gs * a[6]), fmaf(wk, p.y, gs * a[7]));
        o.w = *(unsigned*)&h;
        yout[(size_t)node * 8 + g] = o;
    }
}

// ---------------- launch ----------------
extern "C" void kernel_launch(void* const* d_in, const int* in_sizes, int n_in,
                              void* d_out, int out_size) {
    const float* feat  = (const float*)d_in[0];
    const int*   src32 = (const int*)d_in[1];
    const int*   dst32 = (const int*)d_in[2];
    float* out = (float*)d_out;

    int n = in_sizes[0] / DIM;   // 100000
    int e = in_sizes[1];         // 1000000

    void *p0, *p1, *p2;
    cudaGetSymbolAddress(&p0, g_y0);
    cudaGetSymbolAddress(&p1, g_y1);
    cudaGetSymbolAddress(&p2, g_fh);
    uint4* y0 = (uint4*)p0;
    uint4* y1 = (uint4*)p1;
    uint4* fh = (uint4*)p2;

    // log weights: w[j] = log(BETA + 1 + j)/denom, BETA = 2
    double logs[KSTEPS + 1]; double denom = 0.0;
    for (int j = 0; j <= KSTEPS; j++) { logs[j] = log(3.0 + (double)j); denom += logs[j]; }

    int nb_n = (n + 255) / 256;
    int nb_e = (e + 255) / 256;
    int nblk = (n + 1023) / 1024;     // 98
    int n8   = n * 8;

    k_init0<<<nb_n, 256>>>(src32, n);
    k_count<<<nb_e, 256>>>(src32, dst32, e);
    k_scan1<<<nblk, 1024>>>(feat, n, n8);
    k_scan2<<<1, 128>>>(nblk, e, n);
    k_scan3<<<nblk, 1024>>>(n);
    k_fill <<<nb_e, 256>>>(src32, dst32, e);

    int nb_s = (n8 + 255) / 256;      // quarter-warp per node
    const uint4* yin = fh;            // first step gathers feat directly
    uint4* yout = y0;
    for (int k = KSTEPS - 1; k >= 0; k--) {
        float gs = (k == KSTEPS - 1) ? (float)(logs[KSTEPS] / denom) : 1.0f;
        k_step<<<nb_s, 256>>>(yin, yout, fh, feat, out,
                              (float)(logs[k] / denom), gs, n, k == 0);
        yin = yout;
        yout = (yout == y0) ? y1 : y0;
    }
}

// round 10
// speedup vs baseline: 2.0849x; 1.0409x over previous
#include <cuda_runtime.h>
#include <cuda_fp16.h>
#include <math.h>

#define NN 100000
#define NE 1000000
#define DIM 64
#define KSTEPS 10
#define FULLMASK 0xffffffffu

// lookback state encoding: bits 30..31 = status (0 invalid, 1 AGG, 2 INC)
#define ST_AGG (1u << 30)
#define ST_INC (2u << 30)
#define ST_VAL(x) ((x) & ((1u << 30) - 1))

// ---------------- static scratch (no allocations allowed) ----------------
__device__ int     g_out_deg[NN];
__device__ int     g_in_deg[NN];
__device__ float2  g_norm[NN];              // (src_norm, dst_norm)
__device__ int     g_row_ptr[NN + 1];
__device__ int     g_fill[NN];
__device__ int     g_ecol[NE];              // src ids grouped by dst (CSR)
// state stored as 16B granules: row = 8 x uint4 (64 halves)
__device__ __align__(128) uint4 g_y0[(size_t)NN * 8];
__device__ __align__(128) uint4 g_y1[(size_t)NN * 8];
__device__ __align__(128) uint4 g_fh[(size_t)NN * 8];  // fp16 feat (unscaled)
__device__ __align__(128) uint4 g_z0[(size_t)NN * 8];  // fp16 src_norm*feat
__device__ volatile unsigned g_state[128];  // lookback states
__device__ int     g_is64;

__device__ __forceinline__ int edge_at(const int* __restrict__ b, int i, int is64) {
    return b[is64 ? (i << 1) : i];
}

// ---------------- init: zero counters + dtype detect ----------------
__global__ void k_init0(const int* __restrict__ src32, int n) {
    int i = blockIdx.x * blockDim.x + threadIdx.x;
    if (i < n) { g_out_deg[i] = 0; g_in_deg[i] = 0; g_fill[i] = 0; }
    if (i < 128) g_state[i] = 0;
    if (i == 0) g_is64 = 1;
    if (blockIdx.x == 0) {   // int64 data has all-zero odd 32-bit words
        for (int j = threadIdx.x; j < 1024; j += blockDim.x)
            if (src32[2 * j + 1] != 0) g_is64 = 0;
    }
}

__global__ void k_count(const int* __restrict__ src,
                        const int* __restrict__ dst, int e) {
    int i = blockIdx.x * blockDim.x + threadIdx.x;
    int is64 = g_is64;
    if (i < e) {
        atomicAdd(&g_out_deg[edge_at(src, i, is64)], 1);
        atomicAdd(&g_in_deg[edge_at(dst, i, is64)], 1);
    }
}

// Fused: exclusive scan of in_deg (decoupled lookback, 1 launch) + norm pack
// + fp16 feat caches (unscaled fh, src_norm-scaled z0).
__global__ void __launch_bounds__(1024)
k_scan(const float* __restrict__ feat, int n, int etotal, int n8) {
    __shared__ int sh[1024];
    __shared__ int sh_run;
    int tid = threadIdx.x;
    int b = blockIdx.x;
    int gid = b * 1024 + tid;

    int v = (gid < n) ? g_in_deg[gid] : 0;
    sh[tid] = v;
    __syncthreads();
#pragma unroll
    for (int off = 1; off < 1024; off <<= 1) {
        int t = (tid >= off) ? sh[tid - off] : 0;
        __syncthreads();
        sh[tid] += t;
        __syncthreads();
    }
    int total = sh[1023];

    // publish early so successors' lookback completes fast
    if (tid == 0) {
        unsigned pub = (b == 0) ? (ST_INC | (unsigned)total)
                                : (ST_AGG | (unsigned)total);
        atomicExch((unsigned*)&g_state[b], pub);
        if (b == 0) { sh_run = 0; g_row_ptr[n] = etotal; }
    }

    // bulk work rides along: norms + feat caches
    if (gid < n) {
        g_norm[gid] = make_float2(rsqrtf(fmaxf((float)g_out_deg[gid], 1.0f)),
                                  rsqrtf(fmaxf((float)v, 1.0f)));
    }
    for (int i = gid; i < n8; i += gridDim.x * 1024) {
        int node = i >> 3;
        float sn = rsqrtf(fmaxf((float)g_out_deg[node], 1.0f));
        float4 f0 = *(const float4*)(feat + (size_t)i * 8);
        float4 f1 = *(const float4*)(feat + (size_t)i * 8 + 4);
        uint4 oh, oz;
        __half2 h;
        h = __floats2half2_rn(f0.x, f0.y); oh.x = *(unsigned*)&h;
        h = __floats2half2_rn(f0.z, f0.w); oh.y = *(unsigned*)&h;
        h = __floats2half2_rn(f1.x, f1.y); oh.z = *(unsigned*)&h;
        h = __floats2half2_rn(f1.z, f1.w); oh.w = *(unsigned*)&h;
        g_fh[i] = oh;
        h = __floats2half2_rn(sn * f0.x, sn * f0.y); oz.x = *(unsigned*)&h;
        h = __floats2half2_rn(sn * f0.z, sn * f0.w); oz.y = *(unsigned*)&h;
        h = __floats2half2_rn(sn * f1.x, sn * f1.y); oz.z = *(unsigned*)&h;
        h = __floats2half2_rn(sn * f1.z, sn * f1.w); oz.w = *(unsigned*)&h;
        g_z0[i] = oz;
    }

    // warp-parallel lookback (warp 0)
    if (b > 0 && tid < 32) {
        int lane = tid;
        int running = 0;
        int p = b - 1;
        while (true) {
            int idx = p - lane;
            unsigned s;
            if (idx >= 0) {
                do { s = g_state[idx]; } while ((s >> 30) == 0);
            } else {
                s = ST_INC | 0u;   // virtual predecessor
            }
            unsigned inc_mask = __ballot_sync(FULLMASK, (s >> 30) == 2u);
            bool has_inc = (inc_mask != 0u);
            // FIX: with no INC in the window, ALL 32 lanes contribute (f = 31);
            // previous code dropped the whole window's aggregates.
            int f = has_inc ? (__ffs(inc_mask) - 1) : 31;
            int contrib = (lane <= f) ? (int)ST_VAL(s) : 0;
#pragma unroll
            for (int o = 16; o > 0; o >>= 1)
                contrib += __shfl_xor_sync(FULLMASK, contrib, o);
            running += contrib;
            if (has_inc) break;
            p -= 32;
        }
        if (lane == 0) {
            atomicExch((unsigned*)&g_state[b], ST_INC | (unsigned)(running + total));
            sh_run = running;
        }
    }
    __syncthreads();
    int run = sh_run;
    if (gid < n) g_row_ptr[gid] = run + sh[tid] - v;   // exclusive prefix
}

__global__ void k_fill(const int* __restrict__ src,
                       const int* __restrict__ dst, int e) {
    int i = blockIdx.x * blockDim.x + threadIdx.x;
    int is64 = g_is64;
    if (i < e) {
        int s = edge_at(src, i, is64);
        int d = edge_at(dst, i, is64);
        int pos = g_row_ptr[d] + atomicAdd(&g_fill[d], 1);
        g_ecol[pos] = s;
    }
}

// ---------------- Horner propagation (factored norms) ----------------
// State z[v] = sn[v]*y[v] (fp16). Step:
//   y_new[d] = w_k*f[d] + gs*dn[d]*sum_e z[src];  z_new[d] = sn[d]*y_new[d]
// gs = w_K on the first step (z0 = sn*f), else 1. Last step writes fp32 y.
// QUARTER-WARP (8 lanes) per node; lane owns 16B (8 cols) of the 128B row.
__device__ __forceinline__ void add8(uint4 v, float* a) {
    float2 p;
    p = __half22float2(*(__half2*)&v.x); a[0] += p.x; a[1] += p.y;
    p = __half22float2(*(__half2*)&v.y); a[2] += p.x; a[3] += p.y;
    p = __half22float2(*(__half2*)&v.z); a[4] += p.x; a[5] += p.y;
    p = __half22float2(*(__half2*)&v.w); a[6] += p.x; a[7] += p.y;
}

__global__ void __launch_bounds__(256)
k_step(const uint4* __restrict__ yin, uint4* __restrict__ yout,
       const uint4* __restrict__ fh, const float* __restrict__ feat,
       float* __restrict__ out, float wk, float gs, int n, int last) {
    int t = blockIdx.x * blockDim.x + threadIdx.x;
    int node = t >> 3;        // quarter-warp per node
    if (node >= n) return;
    int g = t & 7;            // granule: cols g*8 .. g*8+7

    int beg = g_row_ptr[node];
    int end = g_row_ptr[node + 1];

    float a[8] = {0.f, 0.f, 0.f, 0.f, 0.f, 0.f, 0.f, 0.f};
    int i = beg;
    for (; i + 2 <= end; i += 2) {
        int s0 = g_ecol[i];
        int s1 = g_ecol[i + 1];
        uint4 v0 = yin[(size_t)s0 * 8 + g];
        uint4 v1 = yin[(size_t)s1 * 8 + g];
        add8(v0, a);
        add8(v1, a);
    }
    if (i < end) {
        uint4 v = yin[(size_t)g_ecol[i] * 8 + g];
        add8(v, a);
    }

    float2 nm = g_norm[node];
    float sc = gs * nm.y;     // gs * dst_norm

    if (last) {
        const float* fp = feat + (size_t)node * DIM + g * 8;
        float* op = out + (size_t)node * DIM + g * 8;
        float4 f0 = *(const float4*)fp;
        float4 f1 = *(const float4*)(fp + 4);
        float4 r0, r1;
        r0.x = fmaf(wk, f0.x, sc * a[0]); r0.y = fmaf(wk, f0.y, sc * a[1]);
        r0.z = fmaf(wk, f0.z, sc * a[2]); r0.w = fmaf(wk, f0.w, sc * a[3]);
        r1.x = fmaf(wk, f1.x, sc * a[4]); r1.y = fmaf(wk, f1.y, sc * a[5]);
        r1.z = fmaf(wk, f1.z, sc * a[6]); r1.w = fmaf(wk, f1.w, sc * a[7]);
        *(float4*)op = r0;
        *(float4*)(op + 4) = r1;
    } else {
        uint4 fv = fh[(size_t)node * 8 + g];
        float sn = nm.x;
        float2 p;
        uint4 o;
        __half2 h;
        p = __half22float2(*(__half2*)&fv.x);
        h = __floats2half2_rn(sn * fmaf(wk, p.x, sc * a[0]),
                              sn * fmaf(wk, p.y, sc * a[1]));
        o.x = *(unsigned*)&h;
        p = __half22float2(*(__half2*)&fv.y);
        h = __floats2half2_rn(sn * fmaf(wk, p.x, sc * a[2]),
                              sn * fmaf(wk, p.y, sc * a[3]));
        o.y = *(unsigned*)&h;
        p = __half22float2(*(__half2*)&fv.z);
        h = __floats2half2_rn(sn * fmaf(wk, p.x, sc * a[4]),
                              sn * fmaf(wk, p.y, sc * a[5]));
        o.z = *(unsigned*)&h;
        p = __half22float2(*(__half2*)&fv.w);
        h = __floats2half2_rn(sn * fmaf(wk, p.x, sc * a[6]),
                              sn * fmaf(wk, p.y, sc * a[7]));
        o.w = *(unsigned*)&h;
        yout[(size_t)node * 8 + g] = o;
    }
}

// ---------------- launch ----------------
extern "C" void kernel_launch(void* const* d_in, const int* in_sizes, int n_in,
                              void* d_out, int out_size) {
    const float* feat  = (const float*)d_in[0];
    const int*   src32 = (const int*)d_in[1];
    const int*   dst32 = (const int*)d_in[2];
    float* out = (float*)d_out;

    int n = in_sizes[0] / DIM;   // 100000
    int e = in_sizes[1];         // 1000000

    void *p0, *p1, *p2, *p3;
    cudaGetSymbolAddress(&p0, g_y0);
    cudaGetSymbolAddress(&p1, g_y1);
    cudaGetSymbolAddress(&p2, g_fh);
    cudaGetSymbolAddress(&p3, g_z0);
    uint4* y0 = (uint4*)p0;
    uint4* y1 = (uint4*)p1;
    uint4* fh = (uint4*)p2;
    uint4* z0 = (uint4*)p3;

    // log weights: w[j] = log(BETA + 1 + j)/denom, BETA = 2
    double logs[KSTEPS + 1]; double denom = 0.0;
    for (int j = 0; j <= KSTEPS; j++) { logs[j] = log(3.0 + (double)j); denom += logs[j]; }

    int nb_n = (n + 255) / 256;
    int nb_e = (e + 255) / 256;
    int nblk = (n + 1023) / 1024;     // 98
    int n8   = n * 8;

    k_init0<<<nb_n, 256>>>(src32, n);
    k_count<<<nb_e, 256>>>(src32, dst32, e);
    k_scan <<<nblk, 1024>>>(feat, n, e, n8);
    k_fill <<<nb_e, 256>>>(src32, dst32, e);

    int nb_s = (n8 + 255) / 256;      // quarter-warp per node
    const uint4* yin = z0;            // first step gathers sn-scaled feat
    uint4* yout = y0;
    for (int k = KSTEPS - 1; k >= 0; k--) {
        float gs = (k == KSTEPS - 1) ? (float)(logs[KSTEPS] / denom) : 1.0f;
        k_step<<<nb_s, 256>>>(yin, yout, fh, feat, out,
                              (float)(logs[k] / denom), gs, n, k == 0);
        yin = yout;
        yout = (yout == y0) ? y1 : y0;
    }
}

// round 11
// speedup vs baseline: 2.1482x; 1.0304x over previous
#include <cuda_runtime.h>
#include <cuda_fp16.h>
#include <math.h>

#define NN 100000
#define NE 1000000
#define DIM 64
#define KSTEPS 10
#define FULLMASK 0xffffffffu

// lookback state encoding: bits 30..31 = status (0 invalid, 1 AGG, 2 INC)
#define ST_AGG (1u << 30)
#define ST_INC (2u << 30)
#define ST_VAL(x) ((x) & ((1u << 30) - 1))

// ---------------- static scratch (no allocations allowed) ----------------
__device__ int     g_out_deg[NN];
__device__ int     g_in_deg[NN];
__device__ float2  g_norm[NN];              // (src_norm, dst_norm)
__device__ int     g_row_ptr[NN + 1];
__device__ int     g_cursor[NN];            // running fill cursor (starts at prefix)
__device__ int     g_ecol[NE];              // src ids grouped by dst (CSR)
// state stored as 16B granules: row = 8 x uint4 (64 halves)
__device__ __align__(128) uint4 g_y0[(size_t)NN * 8];
__device__ __align__(128) uint4 g_y1[(size_t)NN * 8];
__device__ __align__(128) uint4 g_fh[(size_t)NN * 8];  // fp16 feat (unscaled)
__device__ __align__(128) uint4 g_z0[(size_t)NN * 8];  // fp16 src_norm*feat
__device__ volatile unsigned g_state[128];  // lookback states
__device__ int     g_is64;

__device__ __forceinline__ int edge_at(const int* __restrict__ b, int i, int is64) {
    return b[is64 ? (i << 1) : i];
}

// ---------------- init: zero counters + dtype detect ----------------
__global__ void k_init0(const int* __restrict__ src32, int n) {
    int i = blockIdx.x * blockDim.x + threadIdx.x;
    if (i < n) { g_out_deg[i] = 0; g_in_deg[i] = 0; }
    if (i < 128) g_state[i] = 0;
    if (i == 0) g_is64 = 1;
    if (blockIdx.x == 0) {   // int64 data has all-zero odd 32-bit words
        for (int j = threadIdx.x; j < 1024; j += blockDim.x)
            if (src32[2 * j + 1] != 0) g_is64 = 0;
    }
}

__global__ void k_count(const int* __restrict__ src,
                        const int* __restrict__ dst, int e) {
    int i = blockIdx.x * blockDim.x + threadIdx.x;
    int is64 = g_is64;
    if (i < e) {
        atomicAdd(&g_out_deg[edge_at(src, i, is64)], 1);
        atomicAdd(&g_in_deg[edge_at(dst, i, is64)], 1);
    }
}

// Fused: exclusive scan of in_deg (decoupled lookback, 1 launch) + norm pack
// + fp16 feat caches (unscaled fh, src_norm-scaled z0) + cursor init.
__global__ void __launch_bounds__(1024)
k_scan(const float* __restrict__ feat, int n, int etotal, int n8) {
    __shared__ int sh[1024];
    __shared__ int sh_run;
    int tid = threadIdx.x;
    int b = blockIdx.x;
    int gid = b * 1024 + tid;

    int v = (gid < n) ? g_in_deg[gid] : 0;
    sh[tid] = v;
    __syncthreads();
#pragma unroll
    for (int off = 1; off < 1024; off <<= 1) {
        int t = (tid >= off) ? sh[tid - off] : 0;
        __syncthreads();
        sh[tid] += t;
        __syncthreads();
    }
    int total = sh[1023];

    // publish early so successors' lookback completes fast
    if (tid == 0) {
        unsigned pub = (b == 0) ? (ST_INC | (unsigned)total)
                                : (ST_AGG | (unsigned)total);
        atomicExch((unsigned*)&g_state[b], pub);
        if (b == 0) { sh_run = 0; g_row_ptr[n] = etotal; }
    }

    // bulk work rides along: norms + feat caches
    if (gid < n) {
        g_norm[gid] = make_float2(rsqrtf(fmaxf((float)g_out_deg[gid], 1.0f)),
                                  rsqrtf(fmaxf((float)v, 1.0f)));
    }
    for (int i = gid; i < n8; i += gridDim.x * 1024) {
        int node = i >> 3;
        float sn = rsqrtf(fmaxf((float)g_out_deg[node], 1.0f));
        float4 f0 = *(const float4*)(feat + (size_t)i * 8);
        float4 f1 = *(const float4*)(feat + (size_t)i * 8 + 4);
        uint4 oh, oz;
        __half2 h;
        h = __floats2half2_rn(f0.x, f0.y); oh.x = *(unsigned*)&h;
        h = __floats2half2_rn(f0.z, f0.w); oh.y = *(unsigned*)&h;
        h = __floats2half2_rn(f1.x, f1.y); oh.z = *(unsigned*)&h;
        h = __floats2half2_rn(f1.z, f1.w); oh.w = *(unsigned*)&h;
        g_fh[i] = oh;
        h = __floats2half2_rn(sn * f0.x, sn * f0.y); oz.x = *(unsigned*)&h;
        h = __floats2half2_rn(sn * f0.z, sn * f0.w); oz.y = *(unsigned*)&h;
        h = __floats2half2_rn(sn * f1.x, sn * f1.y); oz.z = *(unsigned*)&h;
        h = __floats2half2_rn(sn * f1.z, sn * f1.w); oz.w = *(unsigned*)&h;
        g_z0[i] = oz;
    }

    // warp-parallel lookback (warp 0)
    if (b > 0 && tid < 32) {
        int lane = tid;
        int running = 0;
        int p = b - 1;
        while (true) {
            int idx = p - lane;
            unsigned s;
            if (idx >= 0) {
                do { s = g_state[idx]; } while ((s >> 30) == 0);
            } else {
                s = ST_INC | 0u;   // virtual predecessor
            }
            unsigned inc_mask = __ballot_sync(FULLMASK, (s >> 30) == 2u);
            bool has_inc = (inc_mask != 0u);
            // with no INC in the window, ALL 32 lanes contribute
            int f = has_inc ? (__ffs(inc_mask) - 1) : 31;
            int contrib = (lane <= f) ? (int)ST_VAL(s) : 0;
#pragma unroll
            for (int o = 16; o > 0; o >>= 1)
                contrib += __shfl_xor_sync(FULLMASK, contrib, o);
            running += contrib;
            if (has_inc) break;
            p -= 32;
        }
        if (lane == 0) {
            atomicExch((unsigned*)&g_state[b], ST_INC | (unsigned)(running + total));
            sh_run = running;
        }
    }
    __syncthreads();
    int run = sh_run;
    if (gid < n) {
        int pref = run + sh[tid] - v;   // exclusive prefix
        g_row_ptr[gid] = pref;
        g_cursor[gid]  = pref;          // fill cursor starts at prefix
    }
}

__global__ void k_fill(const int* __restrict__ src,
                       const int* __restrict__ dst, int e) {
    int i = blockIdx.x * blockDim.x + threadIdx.x;
    int is64 = g_is64;
    if (i < e) {
        int s = edge_at(src, i, is64);
        int d = edge_at(dst, i, is64);
        int pos = atomicAdd(&g_cursor[d], 1);   // absolute slot, no extra load
        g_ecol[pos] = s;
    }
}

// ---------------- Horner propagation (factored norms) ----------------
// State z[v] = sn[v]*y[v] (fp16). Step:
//   y_new[d] = w_k*f[d] + gs*dn[d]*sum_e z[src];  z_new[d] = sn[d]*y_new[d]
// gs = w_K on the first step (z0 = sn*f), else 1. Last step writes fp32 y.
// QUARTER-WARP (8 lanes) per node; lane owns 16B (8 cols) of the 128B row.
__device__ __forceinline__ void add8(uint4 v, float* a) {
    float2 p;
    p = __half22float2(*(__half2*)&v.x); a[0] += p.x; a[1] += p.y;
    p = __half22float2(*(__half2*)&v.y); a[2] += p.x; a[3] += p.y;
    p = __half22float2(*(__half2*)&v.z); a[4] += p.x; a[5] += p.y;
    p = __half22float2(*(__half2*)&v.w); a[6] += p.x; a[7] += p.y;
}

__global__ void __launch_bounds__(256)
k_step(const uint4* __restrict__ yin, uint4* __restrict__ yout,
       const uint4* __restrict__ fh, const float* __restrict__ feat,
       float* __restrict__ out, float wk, float gs, int n, int last) {
    int t = blockIdx.x * blockDim.x + threadIdx.x;
    int node = t >> 3;        // quarter-warp per node
    if (node >= n) return;
    int g = t & 7;            // granule: cols g*8 .. g*8+7

    int beg = g_row_ptr[node];
    int end = g_row_ptr[node + 1];

    float a[8] = {0.f, 0.f, 0.f, 0.f, 0.f, 0.f, 0.f, 0.f};
    int i = beg;
    // 4 independent gather chains per quarter (16 per warp) in flight
    for (; i + 4 <= end; i += 4) {
        int s0 = g_ecol[i],     s1 = g_ecol[i + 1];
        int s2 = g_ecol[i + 2], s3 = g_ecol[i + 3];
        uint4 v0 = yin[(size_t)s0 * 8 + g];
        uint4 v1 = yin[(size_t)s1 * 8 + g];
        uint4 v2 = yin[(size_t)s2 * 8 + g];
        uint4 v3 = yin[(size_t)s3 * 8 + g];
        add8(v0, a); add8(v1, a); add8(v2, a); add8(v3, a);
    }
    for (; i + 2 <= end; i += 2) {
        int s0 = g_ecol[i], s1 = g_ecol[i + 1];
        uint4 v0 = yin[(size_t)s0 * 8 + g];
        uint4 v1 = yin[(size_t)s1 * 8 + g];
        add8(v0, a); add8(v1, a);
    }
    if (i < end) {
        uint4 v = yin[(size_t)g_ecol[i] * 8 + g];
        add8(v, a);
    }

    float2 nm = g_norm[node];
    float sc = gs * nm.y;     // gs * dst_norm

    if (last) {
        const float* fp = feat + (size_t)node * DIM + g * 8;
        float* op = out + (size_t)node * DIM + g * 8;
        float4 f0 = *(const float4*)fp;
        float4 f1 = *(const float4*)(fp + 4);
        float4 r0, r1;
        r0.x = fmaf(wk, f0.x, sc * a[0]); r0.y = fmaf(wk, f0.y, sc * a[1]);
        r0.z = fmaf(wk, f0.z, sc * a[2]); r0.w = fmaf(wk, f0.w, sc * a[3]);
        r1.x = fmaf(wk, f1.x, sc * a[4]); r1.y = fmaf(wk, f1.y, sc * a[5]);
        r1.z = fmaf(wk, f1.z, sc * a[6]); r1.w = fmaf(wk, f1.w, sc * a[7]);
        *(float4*)op = r0;
        *(float4*)(op + 4) = r1;
    } else {
        uint4 fv = fh[(size_t)node * 8 + g];
        float sn = nm.x;
        float2 p;
        uint4 o;
        __half2 h;
        p = __half22float2(*(__half2*)&fv.x);
        h = __floats2half2_rn(sn * fmaf(wk, p.x, sc * a[0]),
                              sn * fmaf(wk, p.y, sc * a[1]));
        o.x = *(unsigned*)&h;
        p = __half22float2(*(__half2*)&fv.y);
        h = __floats2half2_rn(sn * fmaf(wk, p.x, sc * a[2]),
                              sn * fmaf(wk, p.y, sc * a[3]));
        o.y = *(unsigned*)&h;
        p = __half22float2(*(__half2*)&fv.z);
        h = __floats2half2_rn(sn * fmaf(wk, p.x, sc * a[4]),
                              sn * fmaf(wk, p.y, sc * a[5]));
        o.z = *(unsigned*)&h;
        p = __half22float2(*(__half2*)&fv.w);
        h = __floats2half2_rn(sn * fmaf(wk, p.x, sc * a[6]),
                              sn * fmaf(wk, p.y, sc * a[7]));
        o.w = *(unsigned*)&h;
        yout[(size_t)node * 8 + g] = o;
    }
}

// ---------------- launch ----------------
extern "C" void kernel_launch(void* const* d_in, const int* in_sizes, int n_in,
                              void* d_out, int out_size) {
    const float* feat  = (const float*)d_in[0];
    const int*   src32 = (const int*)d_in[1];
    const int*   dst32 = (const int*)d_in[2];
    float* out = (float*)d_out;

    int n = in_sizes[0] / DIM;   // 100000
    int e = in_sizes[1];         // 1000000

    void *p0, *p1, *p2, *p3;
    cudaGetSymbolAddress(&p0, g_y0);
    cudaGetSymbolAddress(&p1, g_y1);
    cudaGetSymbolAddress(&p2, g_fh);
    cudaGetSymbolAddress(&p3, g_z0);
    uint4* y0 = (uint4*)p0;
    uint4* y1 = (uint4*)p1;
    uint4* fh = (uint4*)p2;
    uint4* z0 = (uint4*)p3;

    // log weights: w[j] = log(BETA + 1 + j)/denom, BETA = 2
    double logs[KSTEPS + 1]; double denom = 0.0;
    for (int j = 0; j <= KSTEPS; j++) { logs[j] = log(3.0 + (double)j); denom += logs[j]; }

    int nb_n = (n + 255) / 256;
    int nb_e = (e + 255) / 256;
    int nblk = (n + 1023) / 1024;     // 98
    int n8   = n * 8;

    k_init0<<<nb_n, 256>>>(src32, n);
    k_count<<<nb_e, 256>>>(src32, dst32, e);
    k_scan <<<nblk, 1024>>>(feat, n, e, n8);
    k_fill <<<nb_e, 256>>>(src32, dst32, e);

    int nb_s = (n8 + 255) / 256;      // quarter-warp per node
    const uint4* yin = z0;            // first step gathers sn-scaled feat
    uint4* yout = y0;
    for (int k = KSTEPS - 1; k >= 0; k--) {
        float gs = (k == KSTEPS - 1) ? (float)(logs[KSTEPS] / denom) : 1.0f;
        k_step<<<nb_s, 256>>>(yin, yout, fh, feat, out,
                              (float)(logs[k] / denom), gs, n, k == 0);
        yin = yout;
        yout = (yout == y0) ? y1 : y0;
    }
}